// round 8
// baseline (speedup 1.0000x reference)
#include <cuda_runtime.h>
#include <cuda_fp16.h>
#include <cstdint>
#include <math.h>

#define H 2048
#define E 64
#define BM 64
#define NKK (H / 16)    // 128 k16 steps
#define NCH (H / 64)    // 32 chunks of 64 k
#define LSCALE 4096.0f
#define LINV   (1.0f / 4096.0f)

// dynamic smem layout:
//   [0, 32768)      fp16 A planes: buf b at b*16384, plane p at +p*8192
//   [32768, 67584)  fp32 staging ring: stage s at 32768 + s*17408 (64 rows x 272B)
#define FS_OFF 32768
#define FS_STRIDE 17408
#define SMEM_DYN 67584

// ---------------- device globals (no allocation allowed) -------------------
__device__ float g_bias[E];
__device__ float g_cnt[E];
__device__ float g_psum[E];
__device__ unsigned g_done;
// W planes prepacked in mma B-fragment per-lane order:
// index = (kk*8 + gtile)*32 + lane ; {h_b0, h_b1, lScaled_b0, lScaled_b1}
__device__ uint4 g_wp[NKK * 8 * 32];

// ---------------- helpers ---------------------------------------------------
__device__ __forceinline__ uint32_t smem_u32(const void* p) {
    uint32_t a;
    asm("{ .reg .u64 t; cvta.to.shared.u64 t, %1; cvt.u32.u64 %0, t; }" : "=r"(a) : "l"(p));
    return a;
}

__device__ __forceinline__ void cpa16(uint32_t dst, const void* src) {
    asm volatile("cp.async.cg.shared.global [%0], [%1], 16;" :: "r"(dst), "l"(src));
}
#define CP_COMMIT() asm volatile("cp.async.commit_group;" ::: "memory")
#define CP_WAIT1()  asm volatile("cp.async.wait_group 1;" ::: "memory")

// split (f0,f1) -> fp16x2 hi plane + fp16x2 lo plane scaled by 2^12
__device__ __forceinline__ void splitH(float f0, float f1, uint32_t& h, uint32_t& l) {
    __half2 hh = __floats2half2_rn(f0, f1);
    float2 hf = __half22float2(hh);
    __half2 ll = __floats2half2_rn((f0 - hf.x) * LSCALE, (f1 - hf.y) * LSCALE);
    h = *(uint32_t*)&hh;
    l = *(uint32_t*)&ll;
}

__device__ __forceinline__ void mma16816(float* c,
                                         uint32_t a0, uint32_t a1, uint32_t a2, uint32_t a3,
                                         uint32_t b0, uint32_t b1) {
    asm("mma.sync.aligned.m16n8k16.row.col.f32.f16.f16.f32 "
        "{%0,%1,%2,%3}, {%4,%5,%6,%7}, {%8,%9}, {%0,%1,%2,%3};"
        : "+f"(c[0]), "+f"(c[1]), "+f"(c[2]), "+f"(c[3])
        : "r"(a0), "r"(a1), "r"(a2), "r"(a3), "r"(b0), "r"(b1));
}

__device__ __forceinline__ void ldm4(uint32_t& r0, uint32_t& r1,
                                     uint32_t& r2, uint32_t& r3, uint32_t addr) {
    asm volatile("ldmatrix.sync.aligned.m8n8.x4.shared.b16 {%0,%1,%2,%3}, [%4];"
                 : "=r"(r0), "=r"(r1), "=r"(r2), "=r"(r3) : "r"(addr));
}

// ---------------------------------------------------------------------------
// W prep (+ bias init + accumulator reset, folded into block 0)
__global__ __launch_bounds__(256) void wprep_kernel(const float* __restrict__ W,
                                                    const float* __restrict__ rep,
                                                    const float* __restrict__ loads,
                                                    const float* __restrict__ counts,
                                                    const int* __restrict__ total) {
    int id = blockIdx.x * 256 + threadIdx.x;   // 0..32767
    int lane = id & 31;
    int gt = (id >> 5) & 7;
    int kk = id >> 8;
    int n = gt * 8 + (lane >> 2);
    int q = lane & 3;
    int p0 = n * (H / 2) + kk * 8 + q;   // pair index into W
    int p1 = p0 + 4;
    float2 f0 = ((const float2*)W)[p0];
    float2 f1 = ((const float2*)W)[p1];
    uint32_t h0, l0, h1, l1;
    splitH(f0.x, f0.y, h0, l0);
    splitH(f1.x, f1.y, h1, l1);
    g_wp[id] = make_uint4(h0, h1, l0, l1);

    if (blockIdx.x == 0) {
        int t = threadIdx.x;
        if (t < E) {
            float lt = logf((float)(*total) + 1.0f);
            float expl = 0.1f * sqrtf(lt / (counts[t] + 1e-10f));
            float ul = 0.9f * loads[t] + 0.1f * loads[t];   // mirror reference EMA
            g_bias[t] = 0.1f * rep[t] - 0.1f * ul + expl;
            g_cnt[t] = 0.0f;
            g_psum[t] = 0.0f;
        }
        if (t == 64) g_done = 0u;
    }
}

// ---------------------------------------------------------------------------
// Fused GEMM with cp.async fp32 staging ring (2 chunks ahead), smem fp16 plane
// conversion, ldmatrix consumers, 2-deep B register pipeline, fused epilogue.
// BM=64 tokens/CTA, 8 warps: (mg=wid&1) 32 tokens, (ng=wid>>1) 16 experts.
// fp16 A: buf b, plane p at b*16384 + p*8192; row r stride 128B;
//   16B quad qq (0..7, = 8 k) stored at slot qq^(r&7).
// ---------------------------------------------------------------------------
__global__ __launch_bounds__(256, 2) void gemm_kernel(const float* __restrict__ X,
                                                      float* __restrict__ out, int T) {
    extern __shared__ __align__(128) char smA[];
    __shared__ float sB[E], sP[E], sC[E];
    __shared__ float sRed[64];
    __shared__ unsigned s_last;

    int tid = threadIdx.x, lane = tid & 31, wid = tid >> 5;
    int mg = wid & 1, ng = wid >> 1;
    int q = lane & 3;
    if (tid < E) { sB[tid] = g_bias[tid]; sP[tid] = 0.0f; sC[tid] = 0.0f; }

    int tokBase = blockIdx.x * BM;
    uint32_t smb = smem_u32(smA);

    // ---- producer/converter: row = tid/4, 64B fp32 slice sq = tid%4 ----
    int prow = tid >> 2, pq = tid & 3;
    const char* xrow = (const char*)(X + (size_t)(tokBase + prow) * H) + pq * 64;
    uint32_t fsOff = (uint32_t)(prow * 272 + pq * 64);
    uint32_t pBase = (uint32_t)(prow * 128);
    uint32_t slot0 = (uint32_t)(((2 * pq)     ^ (prow & 7)) << 4);
    uint32_t slot1 = (uint32_t)(((2 * pq + 1) ^ (prow & 7)) << 4);

    // ---- consumer ldmatrix lane addressing ----
    int tRow = (lane >> 3) & 1;
    int tCq  = lane >> 4;            // 0/1 -> quad 2j + tCq
    int rB = mg * 32 + tRow * 8 + (lane & 7);
    int e7 = rB & 7;
    uint32_t cBase = smb + (uint32_t)(rB * 128);

    // B fragment pointer (2 n-tiles of 8 experts)
    const uint4* bp = g_wp + (size_t)(ng * 2) * 32 + lane;

    float acc[2][2][4], accL[2][2][4];
#pragma unroll
    for (int s = 0; s < 2; ++s)
#pragma unroll
        for (int t = 0; t < 2; ++t)
#pragma unroll
            for (int c = 0; c < 4; ++c) { acc[s][t][c] = 0.0f; accL[s][t][c] = 0.0f; }

    // ---- prologue: cp.async chunks 0,1; convert chunk 0; B pipeline 2 deep ----
#pragma unroll
    for (int cc = 0; cc < 2; ++cc) {
        uint32_t dst = smb + FS_OFF + (uint32_t)(cc * FS_STRIDE) + fsOff;
        const char* src = xrow + cc * 256;
#pragma unroll
        for (int i = 0; i < 4; ++i) cpa16(dst + i * 16, src + i * 16);
        CP_COMMIT();
    }
    CP_WAIT1();   // chunk 0 arrived
    {
        char* fs = smA + FS_OFF + fsOff;
        float4 f0 = *(float4*)(fs), f1 = *(float4*)(fs + 16);
        float4 f2 = *(float4*)(fs + 32), f3 = *(float4*)(fs + 48);
        uint4 hi0, lo0, hi1, lo1;
        splitH(f0.x, f0.y, hi0.x, lo0.x); splitH(f0.z, f0.w, hi0.y, lo0.y);
        splitH(f1.x, f1.y, hi0.z, lo0.z); splitH(f1.z, f1.w, hi0.w, lo0.w);
        splitH(f2.x, f2.y, hi1.x, lo1.x); splitH(f2.z, f2.w, hi1.y, lo1.y);
        splitH(f3.x, f3.y, hi1.z, lo1.z); splitH(f3.z, f3.w, hi1.w, lo1.w);
        *(uint4*)(smA + pBase + slot0)        = hi0;
        *(uint4*)(smA + pBase + slot0 + 8192) = lo0;
        *(uint4*)(smA + pBase + slot1)        = hi1;
        *(uint4*)(smA + pBase + slot1 + 8192) = lo1;
    }
    uint4 b0[2], b1[2];
    b0[0] = bp[0];   b0[1] = bp[32];
    b1[0] = bp[256]; b1[1] = bp[288];
    __syncthreads();

    for (int c = 0; c < NCH; ++c) {
        uint32_t bufOff = (uint32_t)((c & 1) * 16384);

        // issue cp.async for chunk c+2 into stage (c&1) (freed: chunk c converted)
        if (c + 2 < NCH) {
            uint32_t dst = smb + FS_OFF + (uint32_t)((c & 1) * FS_STRIDE) + fsOff;
            const char* src = xrow + (c + 2) * 256;
#pragma unroll
            for (int i = 0; i < 4; ++i) cpa16(dst + i * 16, src + i * 16);
        }
        CP_COMMIT();
        CP_WAIT1();   // chunk c+1 data resident

        // convert chunk c+1 -> fp16 buf((c+1)&1) (consumers are on buf(c&1))
        if (c + 1 < NCH) {
            char* fs = smA + FS_OFF + ((c + 1) & 1) * FS_STRIDE + fsOff;
            float4 f0 = *(float4*)(fs), f1 = *(float4*)(fs + 16);
            float4 f2 = *(float4*)(fs + 32), f3 = *(float4*)(fs + 48);
            uint4 hi0, lo0, hi1, lo1;
            splitH(f0.x, f0.y, hi0.x, lo0.x); splitH(f0.z, f0.w, hi0.y, lo0.y);
            splitH(f1.x, f1.y, hi0.z, lo0.z); splitH(f1.z, f1.w, hi0.w, lo0.w);
            splitH(f2.x, f2.y, hi1.x, lo1.x); splitH(f2.z, f2.w, hi1.y, lo1.y);
            splitH(f3.x, f3.y, hi1.z, lo1.z); splitH(f3.z, f3.w, hi1.w, lo1.w);
            uint32_t o = (uint32_t)(((c + 1) & 1) * 16384) + pBase;
            *(uint4*)(smA + o + slot0)        = hi0;
            *(uint4*)(smA + o + slot0 + 8192) = lo0;
            *(uint4*)(smA + o + slot1)        = hi1;
            *(uint4*)(smA + o + slot1 + 8192) = lo1;
        }

#pragma unroll
        for (int j = 0; j < 4; ++j) {
            int kkg = c * 4 + j;
            uint4 b[2];
            b[0] = b0[0]; b[1] = b0[1];
            b0[0] = b1[0]; b0[1] = b1[1];
            if (kkg + 2 < NKK) {
                const uint4* p = bp + (size_t)(kkg + 2) * 256;
                b1[0] = p[0]; b1[1] = p[32];
            }

            // ldmatrix A fragments for both s-tiles, both planes
            uint32_t sw = (uint32_t)((((2 * j + tCq) ^ e7) << 4));
            uint32_t ah[2][4], al[2][4];
#pragma unroll
            for (int s = 0; s < 2; ++s) {
                uint32_t addrH = cBase + bufOff + (uint32_t)(s * 16 * 128) + sw;
                ldm4(ah[s][0], ah[s][1], ah[s][2], ah[s][3], addrH);
                ldm4(al[s][0], al[s][1], al[s][2], al[s][3], addrH + 8192);
            }

#pragma unroll
            for (int t = 0; t < 2; ++t) {
                uint32_t bh0 = b[t].x, bh1 = b[t].y;
                uint32_t bl0 = b[t].z, bl1 = b[t].w;
#pragma unroll
                for (int s = 0; s < 2; ++s) {
                    mma16816(acc[s][t],  ah[s][0], ah[s][1], ah[s][2], ah[s][3], bh0, bh1);
                    mma16816(accL[s][t], ah[s][0], ah[s][1], ah[s][2], ah[s][3], bl0, bl1);
                    mma16816(accL[s][t], al[s][0], al[s][1], al[s][2], al[s][3], bh0, bh1);
                }
            }
        }
        __syncthreads();
    }

    // ---- combine planes + store score fragments to smem (alias over smA) ----
    float (*sS)[66] = (float (*)[66])smA;
#pragma unroll
    for (int s = 0; s < 2; ++s) {
        int rr = mg * 32 + s * 16 + (lane >> 2);
#pragma unroll
        for (int t = 0; t < 2; ++t) {
            int cc = ng * 16 + t * 8 + 2 * q;
            *(float2*)&sS[rr][cc] = make_float2(
                acc[s][t][0] + accL[s][t][0] * LINV,
                acc[s][t][1] + accL[s][t][1] * LINV);
            *(float2*)&sS[rr + 8][cc] = make_float2(
                acc[s][t][2] + accL[s][t][2] * LINV,
                acc[s][t][3] + accL[s][t][3] * LINV);
        }
    }
    __syncthreads();

    // ---- per-token epilogue (threads 0..63, one token each) ----
    if (tid < BM) {
        float a = -1e30f, b = -1e30f;
        int ai = 0, bi = 0;
#pragma unroll
        for (int j = 0; j < 64; ++j) {
            float s = sS[tid][j] + sB[j];
            sS[tid][j] = s;
            if (s > a)      { b = a; bi = ai; a = s; ai = j; }
            else if (s > b) { b = s; bi = j; }
        }
        float sum = 0.0f;
#pragma unroll
        for (int j = 0; j < 64; ++j) {
            float e = __expf(sS[tid][j] - a);
            sS[tid][j] = e;
            sum += e;
        }
        float inv = 1.0f / sum;
#pragma unroll
        for (int j = 0; j < 64; ++j) sS[tid][j] *= inv;

        int tok = tokBase + tid;
        float tt = __expf(b - a);
        float w1 = 1.0f / (1.0f + tt);
        out[2 * tok]     = w1;
        out[2 * tok + 1] = tt * w1;
        out[2 * T + 2 * tok]     = (float)ai;
        out[2 * T + 2 * tok + 1] = (float)bi;
        atomicAdd(&sC[ai], 1.0f);
        atomicAdd(&sC[bi], 1.0f);
    }
    __syncthreads();

    // ---- per-expert prob column sums (all 256 threads, 4 slices of 16 rows) ----
    {
        int e = tid & 63, sl = tid >> 6;
        float s = 0.0f;
#pragma unroll
        for (int i = 0; i < 16; ++i)
            s += sS[sl * 16 + i][e];
        atomicAdd(&sP[e], s);
    }
    __syncthreads();
    if (tid < E) {
        atomicAdd(&g_psum[tid], sP[tid]);
        atomicAdd(&g_cnt[tid], sC[tid]);
    }

    // ---- last CTA computes aux loss ----
    if (tid == 0) {
        __threadfence();
        unsigned v = atomicAdd(&g_done, 1u);
        s_last = (v == gridDim.x - 1) ? 1u : 0u;
    }
    __syncthreads();
    if (s_last) {
        if (tid < 64) sRed[tid] = g_cnt[tid] * g_psum[tid];
    }
    __syncthreads();
    if (s_last && tid < 32) {
        float v = sRed[tid] + sRed[tid + 32];
#pragma unroll
        for (int off = 16; off > 0; off >>= 1)
            v += __shfl_xor_sync(0xffffffffu, v, off);
        if (tid == 0) {
            float invT = 1.0f / (float)T;
            out[4 * T] = v * 64.0f * invT * invT;
        }
    }
}

// ---------------------------------------------------------------------------
extern "C" void kernel_launch(void* const* d_in, const int* in_sizes, int n_in,
                              void* d_out, int out_size) {
    const float* x      = (const float*)d_in[0];
    const float* gw     = (const float*)d_in[1];
    const float* rep    = (const float*)d_in[2];
    const float* loads  = (const float*)d_in[3];
    const float* counts = (const float*)d_in[4];
    const int*   total  = (const int*)d_in[5];
    float* out = (float*)d_out;

    int T = in_sizes[0] / H;   // 16384

    cudaFuncSetAttribute(gemm_kernel, cudaFuncAttributeMaxDynamicSharedMemorySize, SMEM_DYN);

    wprep_kernel<<<NKK * 8 * 32 / 256, 256>>>(gw, rep, loads, counts, total);
    gemm_kernel<<<T / BM, 256, SMEM_DYN>>>(x, out, T);
}

// round 9
// speedup vs baseline: 1.0404x; 1.0404x over previous
#include <cuda_runtime.h>
#include <cuda_fp16.h>
#include <cstdint>
#include <math.h>

#define H 2048
#define E 64
#define BM 64
#define NKK (H / 16)    // 128 k16 steps
#define NCH (H / 64)    // 32 chunks of 64 k
#define LSCALE 4096.0f
#define LINV   (1.0f / 4096.0f)

// dynamic smem layout:
//   [0, 32768)      fp16 A planes: buf b at b*16384, plane p at +p*8192
//   [32768, 81920)  B ring: stage s at 32768 + s*16384 (3 stages x 16KB)
#define BR_OFF 32768
#define BR_STRIDE 16384
#define SMEM_DYN 81920

// ---------------- device globals (no allocation allowed) -------------------
__device__ float g_bias[E];
__device__ float g_cnt[E];
__device__ float g_psum[E];
__device__ unsigned g_done;
// W planes prepacked in mma B-fragment per-lane order:
// index = (kk*8 + gtile)*32 + lane ; {h_b0, h_b1, lScaled_b0, lScaled_b1}
__device__ uint4 g_wp[NKK * 8 * 32];

// ---------------- helpers ---------------------------------------------------
__device__ __forceinline__ uint32_t smem_u32(const void* p) {
    uint32_t a;
    asm("{ .reg .u64 t; cvta.to.shared.u64 t, %1; cvt.u32.u64 %0, t; }" : "=r"(a) : "l"(p));
    return a;
}

__device__ __forceinline__ void cpa16(uint32_t dst, const void* src) {
    asm volatile("cp.async.cg.shared.global [%0], [%1], 16;" :: "r"(dst), "l"(src));
}
#define CP_COMMIT() asm volatile("cp.async.commit_group;" ::: "memory")
#define CP_WAIT1()  asm volatile("cp.async.wait_group 1;" ::: "memory")

// split (f0,f1) -> fp16x2 hi plane + fp16x2 lo plane scaled by 2^12
__device__ __forceinline__ void splitH(float f0, float f1, uint32_t& h, uint32_t& l) {
    __half2 hh = __floats2half2_rn(f0, f1);
    float2 hf = __half22float2(hh);
    __half2 ll = __floats2half2_rn((f0 - hf.x) * LSCALE, (f1 - hf.y) * LSCALE);
    h = *(uint32_t*)&hh;
    l = *(uint32_t*)&ll;
}

__device__ __forceinline__ void mma16816(float* c,
                                         uint32_t a0, uint32_t a1, uint32_t a2, uint32_t a3,
                                         uint32_t b0, uint32_t b1) {
    asm("mma.sync.aligned.m16n8k16.row.col.f32.f16.f16.f32 "
        "{%0,%1,%2,%3}, {%4,%5,%6,%7}, {%8,%9}, {%0,%1,%2,%3};"
        : "+f"(c[0]), "+f"(c[1]), "+f"(c[2]), "+f"(c[3])
        : "r"(a0), "r"(a1), "r"(a2), "r"(a3), "r"(b0), "r"(b1));
}

__device__ __forceinline__ void ldm4(uint32_t& r0, uint32_t& r1,
                                     uint32_t& r2, uint32_t& r3, uint32_t addr) {
    asm volatile("ldmatrix.sync.aligned.m8n8.x4.shared.b16 {%0,%1,%2,%3}, [%4];"
                 : "=r"(r0), "=r"(r1), "=r"(r2), "=r"(r3) : "r"(addr));
}

__device__ __forceinline__ uint4 lds128(uint32_t addr) {
    uint4 v;
    asm volatile("ld.shared.v4.u32 {%0,%1,%2,%3}, [%4];"
                 : "=r"(v.x), "=r"(v.y), "=r"(v.z), "=r"(v.w) : "r"(addr));
    return v;
}

// ---------------------------------------------------------------------------
// W prep (+ bias init + accumulator reset, folded into block 0)
__global__ __launch_bounds__(256) void wprep_kernel(const float* __restrict__ W,
                                                    const float* __restrict__ rep,
                                                    const float* __restrict__ loads,
                                                    const float* __restrict__ counts,
                                                    const int* __restrict__ total) {
    int id = blockIdx.x * 256 + threadIdx.x;   // 0..32767
    int lane = id & 31;
    int gt = (id >> 5) & 7;
    int kk = id >> 8;
    int n = gt * 8 + (lane >> 2);
    int q = lane & 3;
    int p0 = n * (H / 2) + kk * 8 + q;   // pair index into W
    int p1 = p0 + 4;
    float2 f0 = ((const float2*)W)[p0];
    float2 f1 = ((const float2*)W)[p1];
    uint32_t h0, l0, h1, l1;
    splitH(f0.x, f0.y, h0, l0);
    splitH(f1.x, f1.y, h1, l1);
    g_wp[id] = make_uint4(h0, h1, l0, l1);

    if (blockIdx.x == 0) {
        int t = threadIdx.x;
        if (t < E) {
            float lt = logf((float)(*total) + 1.0f);
            float expl = 0.1f * sqrtf(lt / (counts[t] + 1e-10f));
            float ul = 0.9f * loads[t] + 0.1f * loads[t];   // mirror reference EMA
            g_bias[t] = 0.1f * rep[t] - 0.1f * ul + expl;
            g_cnt[t] = 0.0f;
            g_psum[t] = 0.0f;
        }
        if (t == 64) g_done = 0u;
    }
}

// ---------------------------------------------------------------------------
// Fused GEMM: A via register prefetch + smem fp16 planes (double-buffered,
// swizzled); B via cp.async 3-stage smem ring (2 chunks ahead, wait AFTER the
// MMA loop); ldmatrix consumers; fused top-2/softmax/aux epilogue.
// BM=64 tokens/CTA, 8 warps: (mg=wid&1) 32 tokens, (ng=wid>>1) 16 experts.
// fp16 A: buf b, plane p at b*16384 + p*8192; row r stride 128B;
//   16B quad qq (0..7, = 8 k) stored at slot qq^(r&7).
// ---------------------------------------------------------------------------
__global__ __launch_bounds__(256, 2) void gemm_kernel(const float* __restrict__ X,
                                                      float* __restrict__ out, int T) {
    extern __shared__ __align__(128) char smA[];
    __shared__ float sB[E], sP[E], sC[E];
    __shared__ float sRed[64];
    __shared__ unsigned s_last;

    int tid = threadIdx.x, lane = tid & 31, wid = tid >> 5;
    int mg = wid & 1, ng = wid >> 1;
    int q = lane & 3;
    if (tid < E) { sB[tid] = g_bias[tid]; sP[tid] = 0.0f; sC[tid] = 0.0f; }

    int tokBase = blockIdx.x * BM;
    uint32_t smb = smem_u32(smA);

    // ---- producer: row = tid/4, quad pair {pq, pq+4} (each quad = 8 k) ----
    int prow = tid >> 2, pq = tid & 3;
    const float4* xg = (const float4*)(X + (size_t)(tokBase + prow) * H) + pq * 2;
    uint32_t pOffA = (uint32_t)(prow * 128 + (((pq)     ^ (prow & 7)) << 4));
    uint32_t pOffB = (uint32_t)(prow * 128 + (((pq + 4) ^ (prow & 7)) << 4));

    // ---- B ring copy assignment: thread copies 4 consecutive uint4 ----
    const uint4* bsrc = g_wp + tid * 4;
    uint32_t bdst = smb + BR_OFF + (uint32_t)(tid * 64);

    // ---- consumer ldmatrix lane addressing ----
    int tRow = (lane >> 3) & 1;
    int tCq  = lane >> 4;            // 0/1 -> quad 2j + tCq
    int rB = mg * 32 + tRow * 8 + (lane & 7);
    int e7 = rB & 7;
    uint32_t cBase = smb + (uint32_t)(rB * 128);

    // consumer B smem offset base for (j, t): ((j*8 + ng*2 + t)*32 + lane)*16
    uint32_t bCons = smb + BR_OFF + (uint32_t)(((ng * 2) * 32 + lane) * 16);

    float acc[2][2][4], accL[2][2][4];
#pragma unroll
    for (int s = 0; s < 2; ++s)
#pragma unroll
        for (int t = 0; t < 2; ++t)
#pragma unroll
            for (int c = 0; c < 4; ++c) { acc[s][t][c] = 0.0f; accL[s][t][c] = 0.0f; }

    // ---- prologue: convert chunk 0; cp.async B chunks 0,1 ----
    {
        float4 f0 = xg[0], f1 = xg[1], f2 = xg[8], f3 = xg[9];
        uint4 hA, lA, hB, lB;
        splitH(f0.x, f0.y, hA.x, lA.x); splitH(f0.z, f0.w, hA.y, lA.y);
        splitH(f1.x, f1.y, hA.z, lA.z); splitH(f1.z, f1.w, hA.w, lA.w);
        splitH(f2.x, f2.y, hB.x, lB.x); splitH(f2.z, f2.w, hB.y, lB.y);
        splitH(f3.x, f3.y, hB.z, lB.z); splitH(f3.z, f3.w, hB.w, lB.w);
        *(uint4*)(smA + pOffA)        = hA;
        *(uint4*)(smA + pOffA + 8192) = lA;
        *(uint4*)(smA + pOffB)        = hB;
        *(uint4*)(smA + pOffB + 8192) = lB;
    }
#pragma unroll
    for (int cc = 0; cc < 2; ++cc) {
        const uint4* src = bsrc + cc * 1024;
        uint32_t dst = bdst + (uint32_t)(cc * BR_STRIDE);
#pragma unroll
        for (int i = 0; i < 4; ++i) cpa16(dst + i * 16, src + i);
        CP_COMMIT();
    }
    CP_WAIT1();   // B chunk 0 resident
    __syncthreads();

    float4 gr0, gr1, gr2, gr3;
    for (int c = 0; c < NCH; ++c) {
        // prefetch A regs for chunk c+1 (used in convert at end of this chunk)
        if (c + 1 < NCH) {
            gr0 = xg[(c + 1) * 16];
            gr1 = xg[(c + 1) * 16 + 1];
            gr2 = xg[(c + 1) * 16 + 8];
            gr3 = xg[(c + 1) * 16 + 9];
        }
        // issue cp.async for B chunk c+2 into stage (c+2)%3
        if (c + 2 < NCH) {
            const uint4* src = bsrc + (c + 2) * 1024;
            uint32_t dst = bdst + (uint32_t)(((c + 2) % 3) * BR_STRIDE);
#pragma unroll
            for (int i = 0; i < 4; ++i) cpa16(dst + i * 16, src + i);
        }
        CP_COMMIT();

        uint32_t bufOff = (uint32_t)((c & 1) * 16384);
        uint32_t bStage = bCons + (uint32_t)((c % 3) * BR_STRIDE);

#pragma unroll
        for (int j = 0; j < 4; ++j) {
            // B fragments from smem ring (2 LDS.128)
            uint4 b[2];
            b[0] = lds128(bStage + (uint32_t)(j * 8 * 32 * 16));
            b[1] = lds128(bStage + (uint32_t)((j * 8 + 1) * 32 * 16));

            // ldmatrix A fragments for both s-tiles, both planes
            uint32_t sw = (uint32_t)((((2 * j + tCq) ^ e7) << 4));
            uint32_t ah[2][4], al[2][4];
#pragma unroll
            for (int s = 0; s < 2; ++s) {
                uint32_t addrH = cBase + bufOff + (uint32_t)(s * 16 * 128) + sw;
                ldm4(ah[s][0], ah[s][1], ah[s][2], ah[s][3], addrH);
                ldm4(al[s][0], al[s][1], al[s][2], al[s][3], addrH + 8192);
            }

#pragma unroll
            for (int t = 0; t < 2; ++t) {
                uint32_t bh0 = b[t].x, bh1 = b[t].y;
                uint32_t bl0 = b[t].z, bl1 = b[t].w;
#pragma unroll
                for (int s = 0; s < 2; ++s) {
                    mma16816(acc[s][t],  ah[s][0], ah[s][1], ah[s][2], ah[s][3], bh0, bh1);
                    mma16816(accL[s][t], ah[s][0], ah[s][1], ah[s][2], ah[s][3], bl0, bl1);
                    mma16816(accL[s][t], al[s][0], al[s][1], al[s][2], al[s][3], bh0, bh1);
                }
            }
        }

        // wait for B chunk c+1 (hidden behind the MMA loop above)
        CP_WAIT1();

        // convert + stage A chunk c+1 into the other fp16 buffer
        if (c + 1 < NCH) {
            uint4 hA, lA, hB, lB;
            splitH(gr0.x, gr0.y, hA.x, lA.x); splitH(gr0.z, gr0.w, hA.y, lA.y);
            splitH(gr1.x, gr1.y, hA.z, lA.z); splitH(gr1.z, gr1.w, hA.w, lA.w);
            splitH(gr2.x, gr2.y, hB.x, lB.x); splitH(gr2.z, gr2.w, hB.y, lB.y);
            splitH(gr3.x, gr3.y, hB.z, lB.z); splitH(gr3.z, gr3.w, hB.w, lB.w);
            uint32_t o = (uint32_t)(((c + 1) & 1) * 16384);
            *(uint4*)(smA + pOffA + o)        = hA;
            *(uint4*)(smA + pOffA + o + 8192) = lA;
            *(uint4*)(smA + pOffB + o)        = hB;
            *(uint4*)(smA + pOffB + o + 8192) = lB;
        }
        __syncthreads();
    }

    // ---- combine planes + store score fragments to smem (alias over smA) ----
    float (*sS)[66] = (float (*)[66])smA;
#pragma unroll
    for (int s = 0; s < 2; ++s) {
        int rr = mg * 32 + s * 16 + (lane >> 2);
#pragma unroll
        for (int t = 0; t < 2; ++t) {
            int cc = ng * 16 + t * 8 + 2 * q;
            *(float2*)&sS[rr][cc] = make_float2(
                acc[s][t][0] + accL[s][t][0] * LINV,
                acc[s][t][1] + accL[s][t][1] * LINV);
            *(float2*)&sS[rr + 8][cc] = make_float2(
                acc[s][t][2] + accL[s][t][2] * LINV,
                acc[s][t][3] + accL[s][t][3] * LINV);
        }
    }
    __syncthreads();

    // ---- per-token epilogue (threads 0..63, one token each) ----
    if (tid < BM) {
        float a = -1e30f, b = -1e30f;
        int ai = 0, bi = 0;
#pragma unroll
        for (int j = 0; j < 64; ++j) {
            float s = sS[tid][j] + sB[j];
            sS[tid][j] = s;
            if (s > a)      { b = a; bi = ai; a = s; ai = j; }
            else if (s > b) { b = s; bi = j; }
        }
        float sum = 0.0f;
#pragma unroll
        for (int j = 0; j < 64; ++j) {
            float e = __expf(sS[tid][j] - a);
            sS[tid][j] = e;
            sum += e;
        }
        float inv = 1.0f / sum;
#pragma unroll
        for (int j = 0; j < 64; ++j) sS[tid][j] *= inv;

        int tok = tokBase + tid;
        float tt = __expf(b - a);
        float w1 = 1.0f / (1.0f + tt);
        out[2 * tok]     = w1;
        out[2 * tok + 1] = tt * w1;
        out[2 * T + 2 * tok]     = (float)ai;
        out[2 * T + 2 * tok + 1] = (float)bi;
        atomicAdd(&sC[ai], 1.0f);
        atomicAdd(&sC[bi], 1.0f);
    }
    __syncthreads();

    // ---- per-expert prob column sums (all 256 threads, 4 slices of 16 rows) ----
    {
        int e = tid & 63, sl = tid >> 6;
        float s = 0.0f;
#pragma unroll
        for (int i = 0; i < 16; ++i)
            s += sS[sl * 16 + i][e];
        atomicAdd(&sP[e], s);
    }
    __syncthreads();
    if (tid < E) {
        atomicAdd(&g_psum[tid], sP[tid]);
        atomicAdd(&g_cnt[tid], sC[tid]);
    }

    // ---- last CTA computes aux loss ----
    if (tid == 0) {
        __threadfence();
        unsigned v = atomicAdd(&g_done, 1u);
        s_last = (v == gridDim.x - 1) ? 1u : 0u;
    }
    __syncthreads();
    if (s_last) {
        if (tid < 64) sRed[tid] = g_cnt[tid] * g_psum[tid];
    }
    __syncthreads();
    if (s_last && tid < 32) {
        float v = sRed[tid] + sRed[tid + 32];
#pragma unroll
        for (int off = 16; off > 0; off >>= 1)
            v += __shfl_xor_sync(0xffffffffu, v, off);
        if (tid == 0) {
            float invT = 1.0f / (float)T;
            out[4 * T] = v * 64.0f * invT * invT;
        }
    }
}

// ---------------------------------------------------------------------------
extern "C" void kernel_launch(void* const* d_in, const int* in_sizes, int n_in,
                              void* d_out, int out_size) {
    const float* x      = (const float*)d_in[0];
    const float* gw     = (const float*)d_in[1];
    const float* rep    = (const float*)d_in[2];
    const float* loads  = (const float*)d_in[3];
    const float* counts = (const float*)d_in[4];
    const int*   total  = (const int*)d_in[5];
    float* out = (float*)d_out;

    int T = in_sizes[0] / H;   // 16384

    cudaFuncSetAttribute(gemm_kernel, cudaFuncAttributeMaxDynamicSharedMemorySize, SMEM_DYN);

    wprep_kernel<<<NKK * 8 * 32 / 256, 256>>>(gw, rep, loads, counts, total);
    gemm_kernel<<<T / BM, 256, SMEM_DYN>>>(x, out, T);
}

// round 10
// speedup vs baseline: 1.0701x; 1.0286x over previous
#include <cuda_runtime.h>
#include <cuda_fp16.h>
#include <cstdint>
#include <math.h>

#define H 2048
#define E 64
#define BM 64
#define NKK (H / 16)    // 128 k16 steps
#define NCH (H / 64)    // 32 chunks of 64 k
#define LSCALE 4096.0f
#define LINV   (1.0f / 4096.0f)

// dynamic smem layout:
//   [0, 32768)      fp16 A planes: buf b at b*16384, plane p at +p*8192
//   [32768, 81920)  B ring: stage s at 32768 + s*16384 (3 stages x 16KB)
#define BR_OFF 32768
#define BR_STRIDE 16384
#define SMEM_DYN 81920

// ---------------- device globals (no allocation allowed) -------------------
__device__ float g_bias[E];
__device__ float g_cnt[E];
__device__ float g_psum[E];
__device__ unsigned g_done;
// W planes prepacked in mma B-fragment per-lane order:
// index = (kk*8 + gtile)*32 + lane ; {h_b0, h_b1, lScaled_b0, lScaled_b1}
__device__ uint4 g_wp[NKK * 8 * 32];

// ---------------- helpers ---------------------------------------------------
__device__ __forceinline__ uint32_t smem_u32(const void* p) {
    uint32_t a;
    asm("{ .reg .u64 t; cvta.to.shared.u64 t, %1; cvt.u32.u64 %0, t; }" : "=r"(a) : "l"(p));
    return a;
}

__device__ __forceinline__ void cpa16(uint32_t dst, const void* src) {
    asm volatile("cp.async.cg.shared.global [%0], [%1], 16;" :: "r"(dst), "l"(src));
}
#define CP_COMMIT() asm volatile("cp.async.commit_group;" ::: "memory")
#define CP_WAIT1()  asm volatile("cp.async.wait_group 1;" ::: "memory")

// split (f0,f1) -> fp16x2 hi plane + fp16x2 lo plane scaled by 2^12
__device__ __forceinline__ void splitH(float f0, float f1, uint32_t& h, uint32_t& l) {
    __half2 hh = __floats2half2_rn(f0, f1);
    float2 hf = __half22float2(hh);
    __half2 ll = __floats2half2_rn((f0 - hf.x) * LSCALE, (f1 - hf.y) * LSCALE);
    h = *(uint32_t*)&hh;
    l = *(uint32_t*)&ll;
}

__device__ __forceinline__ void mma16816(float* c,
                                         uint32_t a0, uint32_t a1, uint32_t a2, uint32_t a3,
                                         uint32_t b0, uint32_t b1) {
    asm("mma.sync.aligned.m16n8k16.row.col.f32.f16.f16.f32 "
        "{%0,%1,%2,%3}, {%4,%5,%6,%7}, {%8,%9}, {%0,%1,%2,%3};"
        : "+f"(c[0]), "+f"(c[1]), "+f"(c[2]), "+f"(c[3])
        : "r"(a0), "r"(a1), "r"(a2), "r"(a3), "r"(b0), "r"(b1));
}

__device__ __forceinline__ void ldm4(uint32_t& r0, uint32_t& r1,
                                     uint32_t& r2, uint32_t& r3, uint32_t addr) {
    asm volatile("ldmatrix.sync.aligned.m8n8.x4.shared.b16 {%0,%1,%2,%3}, [%4];"
                 : "=r"(r0), "=r"(r1), "=r"(r2), "=r"(r3) : "r"(addr));
}

__device__ __forceinline__ uint4 lds128(uint32_t addr) {
    uint4 v;
    asm volatile("ld.shared.v4.u32 {%0,%1,%2,%3}, [%4];"
                 : "=r"(v.x), "=r"(v.y), "=r"(v.z), "=r"(v.w) : "r"(addr));
    return v;
}

// ---------------------------------------------------------------------------
// W prep (+ bias init + accumulator reset, folded into block 0)
__global__ __launch_bounds__(256) void wprep_kernel(const float* __restrict__ W,
                                                    const float* __restrict__ rep,
                                                    const float* __restrict__ loads,
                                                    const float* __restrict__ counts,
                                                    const int* __restrict__ total) {
    int id = blockIdx.x * 256 + threadIdx.x;   // 0..32767
    int lane = id & 31;
    int gt = (id >> 5) & 7;
    int kk = id >> 8;
    int n = gt * 8 + (lane >> 2);
    int q = lane & 3;
    int p0 = n * (H / 2) + kk * 8 + q;   // pair index into W
    int p1 = p0 + 4;
    float2 f0 = ((const float2*)W)[p0];
    float2 f1 = ((const float2*)W)[p1];
    uint32_t h0, l0, h1, l1;
    splitH(f0.x, f0.y, h0, l0);
    splitH(f1.x, f1.y, h1, l1);
    g_wp[id] = make_uint4(h0, h1, l0, l1);

    if (blockIdx.x == 0) {
        int t = threadIdx.x;
        if (t < E) {
            float lt = logf((float)(*total) + 1.0f);
            float expl = 0.1f * sqrtf(lt / (counts[t] + 1e-10f));
            float ul = 0.9f * loads[t] + 0.1f * loads[t];   // mirror reference EMA
            g_bias[t] = 0.1f * rep[t] - 0.1f * ul + expl;
            g_cnt[t] = 0.0f;
            g_psum[t] = 0.0f;
        }
        if (t == 64) g_done = 0u;
    }
}

// ---------------------------------------------------------------------------
// Fused GEMM: A via register prefetch + smem fp16 planes (double-buffered,
// swizzled); B via cp.async 3-stage smem ring; k-split warp layout:
// 8 warps = (mg 0..1: m32) x (ng 0..1: n32) x (ks 0..1: k16-steps {2ks, 2ks+1}
// of each chunk). Partial accumulators reduced through smem at the end.
// fp16 A: buf b, plane p at b*16384 + p*8192; row r stride 128B;
//   16B quad qq (0..7, = 8 k) stored at slot qq^(r&7).
// ---------------------------------------------------------------------------
__global__ __launch_bounds__(256, 2) void gemm_kernel(const float* __restrict__ X,
                                                      float* __restrict__ out, int T) {
    extern __shared__ __align__(128) char smA[];
    __shared__ float sB[E], sP[E], sC[E];
    __shared__ float sRed[64];
    __shared__ unsigned s_last;

    int tid = threadIdx.x, lane = tid & 31, wid = tid >> 5;
    int mg = wid & 1, ng = (wid >> 1) & 1, ks = wid >> 2;
    int q = lane & 3;
    if (tid < E) { sB[tid] = g_bias[tid]; sP[tid] = 0.0f; sC[tid] = 0.0f; }

    int tokBase = blockIdx.x * BM;
    uint32_t smb = smem_u32(smA);

    // ---- producer: row = tid/4, quad pair {pq, pq+4} (each quad = 8 k) ----
    int prow = tid >> 2, pq = tid & 3;
    const float4* xg = (const float4*)(X + (size_t)(tokBase + prow) * H) + pq * 2;
    uint32_t pOffA = (uint32_t)(prow * 128 + (((pq)     ^ (prow & 7)) << 4));
    uint32_t pOffB = (uint32_t)(prow * 128 + (((pq + 4) ^ (prow & 7)) << 4));

    // ---- B ring copy assignment: thread copies 4 consecutive uint4 ----
    const uint4* bsrc = g_wp + tid * 4;
    uint32_t bdst = smb + BR_OFF + (uint32_t)(tid * 64);

    // ---- consumer ldmatrix lane addressing ----
    int tRow = (lane >> 3) & 1;
    int tCq  = lane >> 4;            // 0/1 -> quad 2j + tCq
    int rB = mg * 32 + tRow * 8 + (lane & 7);
    int e7 = rB & 7;
    uint32_t cBase = smb + (uint32_t)(rB * 128);

    // consumer B smem base: gtile = ng*4 + t, addr = ((j*8 + gtile)*32 + lane)*16
    uint32_t bCons = smb + BR_OFF + (uint32_t)(((ng * 4) * 32 + lane) * 16);

    float acc[2][4][4], accL[2][4][4];
#pragma unroll
    for (int s = 0; s < 2; ++s)
#pragma unroll
        for (int t = 0; t < 4; ++t)
#pragma unroll
            for (int c = 0; c < 4; ++c) { acc[s][t][c] = 0.0f; accL[s][t][c] = 0.0f; }

    // ---- prologue: convert chunk 0; cp.async B chunks 0,1 ----
    {
        float4 f0 = xg[0], f1 = xg[1], f2 = xg[8], f3 = xg[9];
        uint4 hA, lA, hB, lB;
        splitH(f0.x, f0.y, hA.x, lA.x); splitH(f0.z, f0.w, hA.y, lA.y);
        splitH(f1.x, f1.y, hA.z, lA.z); splitH(f1.z, f1.w, hA.w, lA.w);
        splitH(f2.x, f2.y, hB.x, lB.x); splitH(f2.z, f2.w, hB.y, lB.y);
        splitH(f3.x, f3.y, hB.z, lB.z); splitH(f3.z, f3.w, hB.w, lB.w);
        *(uint4*)(smA + pOffA)        = hA;
        *(uint4*)(smA + pOffA + 8192) = lA;
        *(uint4*)(smA + pOffB)        = hB;
        *(uint4*)(smA + pOffB + 8192) = lB;
    }
#pragma unroll
    for (int cc = 0; cc < 2; ++cc) {
        const uint4* src = bsrc + cc * 1024;
        uint32_t dst = bdst + (uint32_t)(cc * BR_STRIDE);
#pragma unroll
        for (int i = 0; i < 4; ++i) cpa16(dst + i * 16, src + i);
        CP_COMMIT();
    }
    CP_WAIT1();   // B chunk 0 resident
    __syncthreads();

    float4 gr0, gr1, gr2, gr3;
    for (int c = 0; c < NCH; ++c) {
        // prefetch A regs for chunk c+1 (used in convert at end of this chunk)
        if (c + 1 < NCH) {
            gr0 = xg[(c + 1) * 16];
            gr1 = xg[(c + 1) * 16 + 1];
            gr2 = xg[(c + 1) * 16 + 8];
            gr3 = xg[(c + 1) * 16 + 9];
        }
        // issue cp.async for B chunk c+2 into stage (c+2)%3
        if (c + 2 < NCH) {
            const uint4* src = bsrc + (c + 2) * 1024;
            uint32_t dst = bdst + (uint32_t)(((c + 2) % 3) * BR_STRIDE);
#pragma unroll
            for (int i = 0; i < 4; ++i) cpa16(dst + i * 16, src + i);
        }
        CP_COMMIT();

        uint32_t bufOff = (uint32_t)((c & 1) * 16384);
        uint32_t bStage = bCons + (uint32_t)((c % 3) * BR_STRIDE);

#pragma unroll
        for (int jj = 0; jj < 2; ++jj) {
            int j = ks * 2 + jj;
            // B fragments from smem ring: gtiles ng*4 .. ng*4+3 (4 LDS.128)
            uint4 b[4];
#pragma unroll
            for (int t = 0; t < 4; ++t)
                b[t] = lds128(bStage + (uint32_t)((j * 8 + t) * 32 * 16));

            // ldmatrix A fragments for both s-tiles, both planes
            uint32_t sw = (uint32_t)((((2 * j + tCq) ^ e7) << 4));
            uint32_t ah[2][4], al[2][4];
#pragma unroll
            for (int s = 0; s < 2; ++s) {
                uint32_t addrH = cBase + bufOff + (uint32_t)(s * 16 * 128) + sw;
                ldm4(ah[s][0], ah[s][1], ah[s][2], ah[s][3], addrH);
                ldm4(al[s][0], al[s][1], al[s][2], al[s][3], addrH + 8192);
            }

#pragma unroll
            for (int t = 0; t < 4; ++t) {
                uint32_t bh0 = b[t].x, bh1 = b[t].y;
                uint32_t bl0 = b[t].z, bl1 = b[t].w;
#pragma unroll
                for (int s = 0; s < 2; ++s) {
                    mma16816(acc[s][t],  ah[s][0], ah[s][1], ah[s][2], ah[s][3], bh0, bh1);
                    mma16816(accL[s][t], ah[s][0], ah[s][1], ah[s][2], ah[s][3], bl0, bl1);
                    mma16816(accL[s][t], al[s][0], al[s][1], al[s][2], al[s][3], bh0, bh1);
                }
            }
        }

        // wait for B chunk c+1 (hidden behind the MMA loop above)
        CP_WAIT1();

        // convert + stage A chunk c+1 into the other fp16 buffer
        if (c + 1 < NCH) {
            uint4 hA, lA, hB, lB;
            splitH(gr0.x, gr0.y, hA.x, lA.x); splitH(gr0.z, gr0.w, hA.y, lA.y);
            splitH(gr1.x, gr1.y, hA.z, lA.z); splitH(gr1.z, gr1.w, hA.w, lA.w);
            splitH(gr2.x, gr2.y, hB.x, lB.x); splitH(gr2.z, gr2.w, hB.y, lB.y);
            splitH(gr3.x, gr3.y, hB.z, lB.z); splitH(gr3.z, gr3.w, hB.w, lB.w);
            uint32_t o = (uint32_t)(((c + 1) & 1) * 16384);
            *(uint4*)(smA + pOffA + o)        = hA;
            *(uint4*)(smA + pOffA + o + 8192) = lA;
            *(uint4*)(smA + pOffB + o)        = hB;
            *(uint4*)(smA + pOffB + o + 8192) = lB;
        }
        __syncthreads();
    }

    // ---- k-split reduction + scores into smem (alias over smA) ----
    float (*sS)[66] = (float (*)[66])smA;
    // ks=1 warps write their combined partials first
    if (ks == 1) {
#pragma unroll
        for (int s = 0; s < 2; ++s) {
            int rr = mg * 32 + s * 16 + (lane >> 2);
#pragma unroll
            for (int t = 0; t < 4; ++t) {
                int cc = ng * 32 + t * 8 + 2 * q;
                *(float2*)&sS[rr][cc] = make_float2(
                    acc[s][t][0] + accL[s][t][0] * LINV,
                    acc[s][t][1] + accL[s][t][1] * LINV);
                *(float2*)&sS[rr + 8][cc] = make_float2(
                    acc[s][t][2] + accL[s][t][2] * LINV,
                    acc[s][t][3] + accL[s][t][3] * LINV);
            }
        }
    }
    __syncthreads();
    if (ks == 0) {
#pragma unroll
        for (int s = 0; s < 2; ++s) {
            int rr = mg * 32 + s * 16 + (lane >> 2);
#pragma unroll
            for (int t = 0; t < 4; ++t) {
                int cc = ng * 32 + t * 8 + 2 * q;
                float2 p0 = *(float2*)&sS[rr][cc];
                float2 p1 = *(float2*)&sS[rr + 8][cc];
                *(float2*)&sS[rr][cc] = make_float2(
                    p0.x + acc[s][t][0] + accL[s][t][0] * LINV,
                    p0.y + acc[s][t][1] + accL[s][t][1] * LINV);
                *(float2*)&sS[rr + 8][cc] = make_float2(
                    p1.x + acc[s][t][2] + accL[s][t][2] * LINV,
                    p1.y + acc[s][t][3] + accL[s][t][3] * LINV);
            }
        }
    }
    __syncthreads();

    // ---- per-token epilogue (threads 0..63, one token each) ----
    if (tid < BM) {
        float a = -1e30f, b = -1e30f;
        int ai = 0, bi = 0;
#pragma unroll
        for (int j = 0; j < 64; ++j) {
            float s = sS[tid][j] + sB[j];
            sS[tid][j] = s;
            if (s > a)      { b = a; bi = ai; a = s; ai = j; }
            else if (s > b) { b = s; bi = j; }
        }
        float sum = 0.0f;
#pragma unroll
        for (int j = 0; j < 64; ++j) {
            float e = __expf(sS[tid][j] - a);
            sS[tid][j] = e;
            sum += e;
        }
        float inv = 1.0f / sum;
#pragma unroll
        for (int j = 0; j < 64; ++j) sS[tid][j] *= inv;

        int tok = tokBase + tid;
        float tt = __expf(b - a);
        float w1 = 1.0f / (1.0f + tt);
        out[2 * tok]     = w1;
        out[2 * tok + 1] = tt * w1;
        out[2 * T + 2 * tok]     = (float)ai;
        out[2 * T + 2 * tok + 1] = (float)bi;
        atomicAdd(&sC[ai], 1.0f);
        atomicAdd(&sC[bi], 1.0f);
    }
    __syncthreads();

    // ---- per-expert prob column sums (all 256 threads, 4 slices of 16 rows) ----
    {
        int e = tid & 63, sl = tid >> 6;
        float s = 0.0f;
#pragma unroll
        for (int i = 0; i < 16; ++i)
            s += sS[sl * 16 + i][e];
        atomicAdd(&sP[e], s);
    }
    __syncthreads();
    if (tid < E) {
        atomicAdd(&g_psum[tid], sP[tid]);
        atomicAdd(&g_cnt[tid], sC[tid]);
    }

    // ---- last CTA computes aux loss ----
    if (tid == 0) {
        __threadfence();
        unsigned v = atomicAdd(&g_done, 1u);
        s_last = (v == gridDim.x - 1) ? 1u : 0u;
    }
    __syncthreads();
    if (s_last) {
        if (tid < 64) sRed[tid] = g_cnt[tid] * g_psum[tid];
    }
    __syncthreads();
    if (s_last && tid < 32) {
        float v = sRed[tid] + sRed[tid + 32];
#pragma unroll
        for (int off = 16; off > 0; off >>= 1)
            v += __shfl_xor_sync(0xffffffffu, v, off);
        if (tid == 0) {
            float invT = 1.0f / (float)T;
            out[4 * T] = v * 64.0f * invT * invT;
        }
    }
}

// ---------------------------------------------------------------------------
extern "C" void kernel_launch(void* const* d_in, const int* in_sizes, int n_in,
                              void* d_out, int out_size) {
    const float* x      = (const float*)d_in[0];
    const float* gw     = (const float*)d_in[1];
    const float* rep    = (const float*)d_in[2];
    const float* loads  = (const float*)d_in[3];
    const float* counts = (const float*)d_in[4];
    const int*   total  = (const int*)d_in[5];
    float* out = (float*)d_out;

    int T = in_sizes[0] / H;   // 16384

    cudaFuncSetAttribute(gemm_kernel, cudaFuncAttributeMaxDynamicSharedMemorySize, SMEM_DYN);

    wprep_kernel<<<NKK * 8 * 32 / 256, 256>>>(gw, rep, loads, counts, total);
    gemm_kernel<<<T / BM, 256, SMEM_DYN>>>(x, out, T);
}